// round 2
// baseline (speedup 1.0000x reference)
#include <cuda_runtime.h>
#include <cstdint>

// Problem constants
#define B_    4096
#define T_    512
#define D_    64
#define H_    128
#define A_    8

#define BB    32      // batch rows per cluster
#define JH    64      // hidden units per CTA (cluster of 2 covers H=128)
#define NTHR  256     // 8 warps; warp w owns CTA-local hidden units [w*8, w*8+8)
#define KTOT  192     // fused K: 64 (x_t) + 128 (h)

// Dynamic smem layout:
//   Ws : [192 k][4 g][64 j]  fp32  -> 49152 floats (196608 B)
//   act: [192 k][32 b]       fp32  -> rows 0..63 = x_t[d][b], 64..191 = h[j][b]
#define W_ELEMS    (KTOT * 4 * JH)
#define ACT_ELEMS  (KTOT * BB)
#define SMEM_BYTES ((W_ELEMS + ACT_ELEMS) * 4)   // 221184 B <= 227 KB

// ----------------- helpers -----------------

__device__ __forceinline__ uint32_t s2u(const void* p) {
    uint32_t a;
    asm("{ .reg .u64 t; cvta.to.shared.u64 t, %1; cvt.u32.u64 %0, t; }"
        : "=r"(a) : "l"(p));
    return a;
}

__device__ __forceinline__ void cluster_sync_() {
    asm volatile("barrier.cluster.arrive.aligned;" ::: "memory");
    asm volatile("barrier.cluster.wait.aligned;" ::: "memory");
}

__device__ __forceinline__ unsigned long long pack2(float x, float y) {
    unsigned long long r;
    asm("mov.b64 %0, {%1, %2};" : "=l"(r) : "f"(x), "f"(y));
    return r;
}
__device__ __forceinline__ void unpack2(unsigned long long v, float& x, float& y) {
    asm("mov.b64 {%0, %1}, %2;" : "=f"(x), "=f"(y) : "l"(v));
}

// fast, overflow-safe sigmoid / tanh (~1e-6 accuracy, MUFU-based)
__device__ __forceinline__ float sigf(float x) {
    return __fdividef(1.0f, 1.0f + __expf(-x));   // exp(+inf)->inf, 1/inf->0: safe
}
__device__ __forceinline__ float tanh_f(float x) {
    float e = __expf(-2.0f * fabsf(x));
    float r = __fdividef(1.0f - e, 1.0f + e);
    return copysignf(r, x);
}

// One broadcast weight-pair load + packed f32x2 FMA.
// Byte offset of (g, j-pair p) within the k-row (given wk already includes jb*4):
//   g*JH*4 + p*8
#define WFMA(g, p)                                                                   \
    {                                                                                \
        unsigned long long wv;                                                       \
        asm volatile("ld.shared.b64 %0, [%1+%2];"                                    \
                     : "=l"(wv) : "r"(wk), "n"((g) * JH * 4 + (p) * 8));             \
        asm("fma.rn.f32x2 %0, %1, %2, %0;"                                           \
            : "+l"(acc[(g) * 4 + (p)]) : "l"(wv), "l"(av));                          \
    }

__global__ void __launch_bounds__(NTHR, 1) __cluster_dims__(2, 1, 1)
lstm_fused_kernel(const float* __restrict__ state,   // [B, T, D]
                  const float* __restrict__ W_ih,    // [4H, D]
                  const float* __restrict__ W_hh,    // [4H, H]
                  const float* __restrict__ b_ih,    // [4H]
                  const float* __restrict__ b_hh,    // [4H]
                  const float* __restrict__ W_fc,    // [A, H]
                  const float* __restrict__ b_fc,    // [A]
                  float* __restrict__ out)           // [B, A]
{
    extern __shared__ float smem[];
    float* Ws  = smem;               // [(k*4 + g)*64 + jl]
    float* act = smem + W_ELEMS;     // [k*32 + b]

    const int tid  = threadIdx.x;
    const int lane = tid & 31;       // batch row within chunk
    const int warp = tid >> 5;       // 0..7
    const int jb   = warp * 8;       // CTA-local j base for this warp
    const int d0   = warp * 8;       // x-dims owned for load/store

    uint32_t rank;
    asm("mov.u32 %0, %%cluster_ctarank;" : "=r"(rank));
    const int b0  = (blockIdx.x >> 1) * BB;   // global batch base of this cluster
    const int jg0 = (int)rank * JH;           // this CTA's global j offset (0 or 64)

    // ---- Fill Ws (coalesced over k in global memory) ----
    // x-part: k in [0,64):  Ws[(k*4+g)*64+jl] = W_ih[(g*H + jg0+jl)*D + k]
    for (int e = tid; e < 4 * JH * D_; e += NTHR) {
        int k  = e & 63;
        int rl = e >> 6;
        int g  = rl >> 6;
        int jl = rl & 63;
        Ws[(k * 4 + g) * JH + jl] = W_ih[(g * H_ + jg0 + jl) * D_ + k];
    }
    // h-part: k in [64,192): Ws[((64+k)*4+g)*64+jl] = W_hh[(g*H + jg0+jl)*H + k]
    for (int e = tid; e < 4 * JH * H_; e += NTHR) {
        int k  = e & 127;
        int rl = e >> 7;
        int g  = rl >> 6;
        int jl = rl & 63;
        Ws[((64 + k) * 4 + g) * JH + jl] = W_hh[(g * H_ + jg0 + jl) * H_ + k];
    }

    // ---- init act: h rows (64..191) = 0 ----
    for (int e = tid; e < H_ * BB; e += NTHR)
        act[(D_ + (e >> 5)) * BB + (e & 31)] = 0.0f;

    // ---- x_0 into act rows 0..63 (thread: batch=lane, dims d0..d0+7) ----
    {
        const float* xr = state + (size_t)(b0 + lane) * T_ * D_ + d0;
        float4 xa = *(const float4*)(xr);
        float4 xb = *(const float4*)(xr + 4);
        act[(d0 + 0) * BB + lane] = xa.x;  act[(d0 + 1) * BB + lane] = xa.y;
        act[(d0 + 2) * BB + lane] = xa.z;  act[(d0 + 3) * BB + lane] = xa.w;
        act[(d0 + 4) * BB + lane] = xb.x;  act[(d0 + 5) * BB + lane] = xb.y;
        act[(d0 + 6) * BB + lane] = xb.z;  act[(d0 + 7) * BB + lane] = xb.w;
    }

    // ---- bias preload, packed to match acc layout ----
    unsigned long long bias2[16];
#pragma unroll
    for (int g = 0; g < 4; g++)
#pragma unroll
        for (int p = 0; p < 4; p++) {
            int r = g * H_ + jg0 + jb + 2 * p;
            bias2[g * 4 + p] = pack2(b_ih[r] + b_hh[r], b_ih[r + 1] + b_hh[r + 1]);
        }

    float c[8];
#pragma unroll
    for (int i = 0; i < 8; i++) c[i] = 0.0f;

    const uint32_t act_u = s2u(act);
    const uint32_t W_u   = s2u(Ws);
    const uint32_t ak0   = act_u + lane * 4;
    const uint32_t wk0   = W_u + jb * 4;
    // my h-store base: row (64 + jg0 + jb), column lane; +128 B per j
    const uint32_t h0addr = act_u + (uint32_t)(D_ + jg0 + jb) * BB * 4 + lane * 4;
    const uint32_t peer   = rank ^ 1u;

    __syncthreads();   // Ws/act init visible CTA-locally before first compute

    for (int t = 0; t < T_; t++) {
        // prefetch x_{t+1} into registers (consumed after cluster sync #1)
        float4 xa, xb;
        if (t < T_ - 1) {
            const float4* xp = (const float4*)(state + (size_t)(b0 + lane) * T_ * D_
                                               + (t + 1) * D_ + d0);
            xa = xp[0];
            xb = xp[1];
        }

        // ---- gates = Ws^T * act + bias (per-thread 8j x 4g, packed pairs) ----
        unsigned long long acc[16];
#pragma unroll
        for (int i = 0; i < 16; i++) acc[i] = bias2[i];

        uint32_t ak = ak0, wk = wk0;
#pragma unroll 4
        for (int k = 0; k < KTOT; k++) {
            float a;
            asm volatile("ld.shared.f32 %0, [%1];" : "=f"(a) : "r"(ak));
            unsigned long long av = pack2(a, a);
            WFMA(0, 0) WFMA(0, 1) WFMA(0, 2) WFMA(0, 3)
            WFMA(1, 0) WFMA(1, 1) WFMA(1, 2) WFMA(1, 3)
            WFMA(2, 0) WFMA(2, 1) WFMA(2, 2) WFMA(2, 3)
            WFMA(3, 0) WFMA(3, 1) WFMA(3, 2) WFMA(3, 3)
            ak += BB * 4;
            wk += 4 * JH * 4;
        }

        // ---- activations: i,f,g,o -> c, h ----
        float hv[8];
#pragma unroll
        for (int p = 0; p < 4; p++) {
            float i0, i1, f0, f1, g0, g1, o0, o1;
            unpack2(acc[0 * 4 + p], i0, i1);
            unpack2(acc[1 * 4 + p], f0, f1);
            unpack2(acc[2 * 4 + p], g0, g1);
            unpack2(acc[3 * 4 + p], o0, o1);
            {
                int jj = 2 * p;
                float cn = sigf(f0) * c[jj] + sigf(i0) * tanh_f(g0);
                c[jj] = cn;
                hv[jj] = sigf(o0) * tanh_f(cn);
            }
            {
                int jj = 2 * p + 1;
                float cn = sigf(f1) * c[jj] + sigf(i1) * tanh_f(g1);
                c[jj] = cn;
                hv[jj] = sigf(o1) * tanh_f(cn);
            }
        }

        cluster_sync_();   // #1: everyone (both CTAs) done READING act

        // store my h slice: local smem + peer smem (same offsets, disjoint rows)
#pragma unroll
        for (int jj = 0; jj < 8; jj++) {
            uint32_t addr = h0addr + (uint32_t)jj * BB * 4;
            asm volatile("st.shared.f32 [%0], %1;" :: "r"(addr), "f"(hv[jj]) : "memory");
            asm volatile("{ .reg .u32 ra; mapa.shared::cluster.u32 ra, %0, %1; "
                         "st.shared::cluster.f32 [ra], %2; }"
                         :: "r"(addr), "r"(peer), "f"(hv[jj]) : "memory");
        }
        // store x_{t+1}
        if (t < T_ - 1) {
            act[(d0 + 0) * BB + lane] = xa.x;  act[(d0 + 1) * BB + lane] = xa.y;
            act[(d0 + 2) * BB + lane] = xa.z;  act[(d0 + 3) * BB + lane] = xa.w;
            act[(d0 + 4) * BB + lane] = xb.x;  act[(d0 + 5) * BB + lane] = xb.y;
            act[(d0 + 6) * BB + lane] = xb.z;  act[(d0 + 7) * BB + lane] = xb.w;
        }

        cluster_sync_();   // #2: all writes (incl. remote h) visible before next read
    }

    // ---- FC epilogue: out = tanh(h @ W_fc^T + b_fc); split A=8 over ranks ----
    // act rows 64..191 now hold the final h for ALL 128 units in each CTA.
    if (warp < 4) {
        int a = (int)rank * 4 + warp;
        float s = b_fc[a];
        const float* wf = W_fc + a * H_;
#pragma unroll 8
        for (int j = 0; j < H_; j++)
            s += act[(D_ + j) * BB + lane] * wf[j];
        out[(b0 + lane) * A_ + a] = tanhf(s);
    }
}

extern "C" void kernel_launch(void* const* d_in, const int* in_sizes, int n_in,
                              void* d_out, int out_size) {
    (void)in_sizes; (void)n_in; (void)out_size;
    cudaFuncSetAttribute(lstm_fused_kernel,
                         cudaFuncAttributeMaxDynamicSharedMemorySize, SMEM_BYTES);
    const float* state = (const float*)d_in[0];
    const float* W_ih  = (const float*)d_in[1];
    const float* W_hh  = (const float*)d_in[2];
    const float* b_ih  = (const float*)d_in[3];
    const float* b_hh  = (const float*)d_in[4];
    const float* W_fc  = (const float*)d_in[5];
    const float* b_fc  = (const float*)d_in[6];

    dim3 grid((B_ / BB) * 2);   // 256 CTAs = 128 clusters of 2
    lstm_fused_kernel<<<grid, NTHR, SMEM_BYTES>>>(
        state, W_ih, W_hh, b_ih, b_hh, W_fc, b_fc, (float*)d_out);
}